// round 8
// baseline (speedup 1.0000x reference)
#include <cuda_runtime.h>
#include <math.h>
#include <float.h>

// SemanticLSTM, GB300 fp32 baseline.
// B=64, T=80 (79 output steps), INPUT=HIDDEN=EMBED=512, SEM=300, CNN=2048, V=10000.
//
// Inputs (metadata order):
//  0 captions(i32 64x80) 1 cnn(64x2048) 2 semantics(64x300)
//  3 Wa(4,512,512) 4 Wb(4,300,512) 5 Wc(4,512,512) 6 Ca(4,2048,512) 7 Cb(4,300,512)
//  8 Cc(4,512,512) 9 Ua(4,512,512) 10 Ub(4,300,512) 11 Uc(4,512,512) 12 bias(4,512)
// 13 embed(10000,512) 14 W_last(512,10000) 15 b_last(10000)
// out: float32 (64, 79, 10000)

#define TSTEPS 79
#define NVOC   10000

// ---------------- scratch (__device__ globals; no allocation) ----------------
__device__ float g_bmul [64*4*1024];   // [b][g][k'] : k'<512 -> bx, k'>=512 -> bh
__device__ float g_bv   [64*4*512];    // bv
__device__ float g_vbias[64*4*512];    // v_feat + bias (time-invariant)
__device__ float g_avp  [4][64*4*512]; // av split-K partials
__device__ float g_s1p  [2][64*4*1024];// raw ax/ah split-K partials (pre bx/bh scale)
__device__ float g_s2p  [4][64*4*512]; // pre split-K partials
__device__ float g_lp   [4][64*NVOC];  // logits split-K partials
__device__ float g_ht   [64*512];
__device__ float g_ct   [64*512];
__device__ float g_pmax [64*10];
__device__ int   g_pidx [64*10];
__device__ int   g_cap  [64];

// ---------------- helpers ----------------
__device__ __forceinline__ float4 f4z() { return make_float4(0.f, 0.f, 0.f, 0.f); }
__device__ __forceinline__ float4 f4add(float4 a, float4 b) {
    return make_float4(a.x+b.x, a.y+b.y, a.z+b.z, a.w+b.w);
}
__device__ __forceinline__ float4 f4mul(float4 a, float4 b) {
    return make_float4(a.x*b.x, a.y*b.y, a.z*b.z, a.w*b.w);
}
__device__ __forceinline__ float4 ld4(const float* p) {
    return *reinterpret_cast<const float4*>(p);
}

// ---------------- shared 64(M) x 64(N) tile GEMM core ----------------
// 256 threads, 4x4 micro-tile per thread. Software prefetch of the next k-tile
// (LDG issued before the FMA loop) hides L2 latency. As is k-major with stride
// 68 (16B-aligned, bank-shifted). loadA4(m,k)/loadB4(k,n) return zero-padded
// float4 fragments; K may be any value (guards in the lambdas).
template<class FA, class FB>
__device__ __forceinline__ void gemm_core(int K, FA loadA4, FB loadB4, float acc[4][4])
{
    __shared__ float As[16][68];
    __shared__ float Bs[16][64];
    const int tid = threadIdx.x;
    const int am  = tid >> 2;          // 0..63  (A row)
    const int ak  = (tid & 3) << 2;    // 0,4,8,12
    const int bk  = tid >> 4;          // 0..15
    const int bn  = (tid & 15) << 2;   // 0..60
    const int tx  = tid & 15;
    const int ty  = tid >> 4;
    const int iters = (K + 15) >> 4;

    float4 a = loadA4(am, ak);
    float4 b = loadB4(bk, bn);
    for (int it = 0; it < iters; ++it) {
        __syncthreads();
        As[ak + 0][am] = a.x;
        As[ak + 1][am] = a.y;
        As[ak + 2][am] = a.z;
        As[ak + 3][am] = a.w;
        *reinterpret_cast<float4*>(&Bs[bk][bn]) = b;
        __syncthreads();
        if (it + 1 < iters) {
            const int k0 = (it + 1) << 4;
            a = loadA4(am, k0 + ak);
            b = loadB4(k0 + bk, bn);
        }
#pragma unroll
        for (int kk = 0; kk < 16; ++kk) {
            float4 av = *reinterpret_cast<const float4*>(&As[kk][ty << 2]);
            float4 bv = *reinterpret_cast<const float4*>(&Bs[kk][tx << 2]);
            float ar[4] = {av.x, av.y, av.z, av.w};
            float br[4] = {bv.x, bv.y, bv.z, bv.w};
#pragma unroll
            for (int r = 0; r < 4; ++r)
#pragma unroll
                for (int c = 0; c < 4; ++c)
                    acc[r][c] = fmaf(ar[r], br[c], acc[r][c]);
        }
    }
}

// ---------------- precompute: bx / bh / bv (semantics @ {Wb,Ub,Cb}[g]) ------
__global__ void k_pre1(const float* __restrict__ sem,
                       const float* __restrict__ Wb,
                       const float* __restrict__ Ub,
                       const float* __restrict__ Cb)
{
    const int nt = blockIdx.x;                 // 0..7  (N tile of 64)
    const int gm = blockIdx.y;                 // 0..11
    const int w  = gm >> 2, g = gm & 3;
    const float* B = (w == 0 ? Wb : (w == 1 ? Ub : Cb)) + g * (300 * 512);
    const int ncol0 = nt << 6;

    float acc[4][4] = {};
    auto la = [&](int m, int k) -> float4 {
        const float* p = sem + m * 300;
        if (k + 4 <= 300) return ld4(p + k);
        float4 r = f4z();
        if (k + 0 < 300) r.x = p[k + 0];
        if (k + 1 < 300) r.y = p[k + 1];
        if (k + 2 < 300) r.z = p[k + 2];
        if (k + 3 < 300) r.w = p[k + 3];
        return r;
    };
    auto lb = [&](int k, int n) -> float4 {
        if (k < 300) return ld4(B + k * 512 + ncol0 + n);
        return f4z();
    };
    gemm_core(300, la, lb, acc);

    const int tx = threadIdx.x & 15, ty = threadIdx.x >> 4;
#pragma unroll
    for (int r = 0; r < 4; ++r) {
        const int b = (ty << 2) + r;
#pragma unroll
        for (int c = 0; c < 4; ++c) {
            const int n = ncol0 + (tx << 2) + c;
            const float v = acc[r][c];
            if (w == 0)      g_bmul[b * 4096 + g * 1024 + n]       = v;
            else if (w == 1) g_bmul[b * 4096 + g * 1024 + 512 + n] = v;
            else             g_bv  [b * 2048 + g * 512 + n]        = v;
        }
    }
}

// ---------------- precompute: av (cnn @ Ca[g]) split-K 4 ----------------
__global__ void k_pre2(const float* __restrict__ cnn, const float* __restrict__ Ca)
{
    const int nt = blockIdx.x, g = blockIdx.y, z = blockIdx.z;
    const int ncol0 = nt << 6;
    const int kc0   = z << 9;                  // *512
    const float* B  = Ca + g * (2048 * 512);

    float acc[4][4] = {};
    auto la = [&](int m, int k) { return ld4(cnn + m * 2048 + kc0 + k); };
    auto lb = [&](int k, int n) { return ld4(B + (kc0 + k) * 512 + ncol0 + n); };
    gemm_core(512, la, lb, acc);

    const int tx = threadIdx.x & 15, ty = threadIdx.x >> 4;
#pragma unroll
    for (int r = 0; r < 4; ++r) {
        const int b = (ty << 2) + r;
#pragma unroll
        for (int c = 0; c < 4; ++c)
            g_avp[z][b * 2048 + g * 512 + ncol0 + (tx << 2) + c] = acc[r][c];
    }
}

// ---------------- precompute: v_feat + bias = ((av)*bv) @ Cc[g] + bias ------
__global__ void k_pre3(const float* __restrict__ Cc, const float* __restrict__ bias)
{
    const int nt = blockIdx.x, g = blockIdx.y;
    const int ncol0 = nt << 6;
    const float* B  = Cc + g * 262144;

    float acc[4][4] = {};
    auto la = [&](int m, int k) -> float4 {
        const int idx = m * 2048 + g * 512 + k;
        float4 s = f4add(f4add(ld4(g_avp[0] + idx), ld4(g_avp[1] + idx)),
                         f4add(ld4(g_avp[2] + idx), ld4(g_avp[3] + idx)));
        return f4mul(s, ld4(g_bv + idx));
    };
    auto lb = [&](int k, int n) { return ld4(B + k * 512 + ncol0 + n); };
    gemm_core(512, la, lb, acc);

    const int tx = threadIdx.x & 15, ty = threadIdx.x >> 4;
#pragma unroll
    for (int r = 0; r < 4; ++r) {
        const int b = (ty << 2) + r;
#pragma unroll
        for (int c = 0; c < 4; ++c) {
            const int n = ncol0 + (tx << 2) + c;
            g_vbias[b * 2048 + g * 512 + n] = acc[r][c] + bias[g * 512 + n];
        }
    }
}

// ---------------- init: h0 = c0 = 0, cap = captions[:,0] ----------------
__global__ void k_init(const int* __restrict__ captions)
{
    const int idx = blockIdx.x * 256 + threadIdx.x;
    if (idx < 64 * 512) { g_ht[idx] = 0.f; g_ct[idx] = 0.f; }
    if (idx < 64) g_cap[idx] = captions[idx * 80];
}

// ---------------- step S1: raw ax / ah partials (split-K 2) ----------------
__global__ void k_s1(const float* __restrict__ embed,
                     const float* __restrict__ Wa,
                     const float* __restrict__ Ua)
{
    const int nt   = blockIdx.x;               // 0..7
    const int gm   = blockIdx.y;               // 0..7
    const int z    = blockIdx.z;               // 0..1
    const int part = gm >> 2, g = gm & 3;      // 0: x path (embed@Wa), 1: h path (ht@Ua)
    const int ncol0 = nt << 6;
    const int kc0   = z << 8;                  // *256
    const float* B  = (part ? Ua : Wa) + g * 262144;

    float acc[4][4] = {};
    auto la = [&](int m, int k) -> float4 {
        const float* p = part ? (g_ht + m * 512) : (embed + g_cap[m] * 512);
        return ld4(p + kc0 + k);
    };
    auto lb = [&](int k, int n) { return ld4(B + (kc0 + k) * 512 + ncol0 + n); };
    gemm_core(256, la, lb, acc);

    const int tx = threadIdx.x & 15, ty = threadIdx.x >> 4;
#pragma unroll
    for (int r = 0; r < 4; ++r) {
        const int b = (ty << 2) + r;
#pragma unroll
        for (int c = 0; c < 4; ++c) {
            const int n = ncol0 + (tx << 2) + c;
            g_s1p[z][b * 4096 + g * 1024 + part * 512 + n] = acc[r][c];
        }
    }
}

// ---------------- step S2: pre partials = (u * bmul) @ [Wc;Uc] (split-K 4) --
__global__ void k_s2(const float* __restrict__ Wc, const float* __restrict__ Uc)
{
    const int nt = blockIdx.x;                 // 0..7
    const int g  = blockIdx.y;                 // 0..3
    const int z  = blockIdx.z;                 // 0..3
    const int ncol0 = nt << 6;
    const int kc0   = z << 8;                  // k' = kc0 + k, k' in [0,1024)
    const float* B  = (z < 2) ? (Wc + g * 262144 + kc0 * 512)
                              : (Uc + g * 262144 + (kc0 - 512) * 512);

    float acc[4][4] = {};
    auto la = [&](int m, int k) -> float4 {
        const int idx = m * 4096 + g * 1024 + kc0 + k;
        float4 s = f4add(ld4(g_s1p[0] + idx), ld4(g_s1p[1] + idx));
        return f4mul(s, ld4(g_bmul + idx));
    };
    auto lb = [&](int k, int n) { return ld4(B + k * 512 + ncol0 + n); };
    gemm_core(256, la, lb, acc);

    const int tx = threadIdx.x & 15, ty = threadIdx.x >> 4;
#pragma unroll
    for (int r = 0; r < 4; ++r) {
        const int b = (ty << 2) + r;
#pragma unroll
        for (int c = 0; c < 4; ++c)
            g_s2p[z][b * 2048 + g * 512 + ncol0 + (tx << 2) + c] = acc[r][c];
    }
}

// ---------------- step gates: pre -> (i,f,o,g) -> ct, ht ----------------
__global__ void k_gates()
{
    const int idx = blockIdx.x * 256 + threadIdx.x; // 0..32767 = b*512 + h
    const int b = idx >> 9, h = idx & 511;
    float pre[4];
#pragma unroll
    for (int g = 0; g < 4; ++g) {
        const int base = b * 2048 + g * 512 + h;
        pre[g] = g_s2p[0][base] + g_s2p[1][base] + g_s2p[2][base] + g_s2p[3][base]
               + g_vbias[base];
    }
    const float ig = 1.f / (1.f + expf(-pre[0]));
    const float fg = 1.f / (1.f + expf(-pre[1]));
    const float og = 1.f / (1.f + expf(-pre[2]));
    const float gg = tanhf(pre[3]);
    const float c  = fg * g_ct[idx] + ig * gg;
    g_ct[idx] = c;
    g_ht[idx] = og * tanhf(c);
}

// ---------------- step S3: logits partials (ht @ W_last, split-K 4) ---------
__global__ void k_s3(const float* __restrict__ Wl)
{
    const int nt = blockIdx.x;                 // 0..156
    const int z  = blockIdx.y;                 // 0..3
    const int ncol0 = nt << 6;
    const int kc0   = z << 7;                  // *128

    float acc[4][4] = {};
    auto la = [&](int m, int k) { return ld4(g_ht + m * 512 + kc0 + k); };
    auto lb = [&](int k, int n) -> float4 {
        const int col = ncol0 + n;
        if (col < NVOC) return ld4(Wl + (kc0 + k) * NVOC + col);  // col mult of 4, NVOC mult of 4
        return f4z();
    };
    gemm_core(128, la, lb, acc);

    const int tx = threadIdx.x & 15, ty = threadIdx.x >> 4;
#pragma unroll
    for (int r = 0; r < 4; ++r) {
        const int b = (ty << 2) + r;
#pragma unroll
        for (int c = 0; c < 4; ++c) {
            const int col = ncol0 + (tx << 2) + c;
            if (col < NVOC) g_lp[z][b * NVOC + col] = acc[r][c];
        }
    }
}

// ---------------- step: combine partials + bias, write out, partial argmax --
__global__ void k_logits(const float* __restrict__ bl, float* __restrict__ out, int t)
{
    const int seg = blockIdx.x;                // 0..9 (1024 cols each)
    const int b   = blockIdx.y;                // 0..63
    const int c0  = seg * 1024 + threadIdx.x * 4;

    float best = -FLT_MAX;
    int   bi   = 0x7FFFFFFF;
    if (c0 < NVOC) {                           // c0 mult of 4 -> full float4 valid
        const int base = b * NVOC + c0;
        float4 v0 = ld4(g_lp[0] + base);
        float4 v1 = ld4(g_lp[1] + base);
        float4 v2 = ld4(g_lp[2] + base);
        float4 v3 = ld4(g_lp[3] + base);
        float4 bb = ld4(bl + c0);
        float v[4] = { v0.x + v1.x + v2.x + v3.x + bb.x,
                       v0.y + v1.y + v2.y + v3.y + bb.y,
                       v0.z + v1.z + v2.z + v3.z + bb.z,
                       v0.w + v1.w + v2.w + v3.w + bb.w };
        *reinterpret_cast<float4*>(out + (b * TSTEPS + t) * NVOC + c0) =
            make_float4(v[0], v[1], v[2], v[3]);
#pragma unroll
        for (int j = 0; j < 4; ++j)
            if (v[j] > best) { best = v[j]; bi = c0 + j; }   // strict > : first index wins
    }

    __shared__ float sv[256];
    __shared__ int   si[256];
    sv[threadIdx.x] = best;
    si[threadIdx.x] = bi;
    __syncthreads();
    for (int s = 128; s; s >>= 1) {
        if (threadIdx.x < s) {
            const float ov = sv[threadIdx.x + s];
            const int   oi = si[threadIdx.x + s];
            if (ov > sv[threadIdx.x] || (ov == sv[threadIdx.x] && oi < si[threadIdx.x])) {
                sv[threadIdx.x] = ov; si[threadIdx.x] = oi;
            }
        }
        __syncthreads();
    }
    if (threadIdx.x == 0) { g_pmax[b * 10 + seg] = sv[0]; g_pidx[b * 10 + seg] = si[0]; }
}

// ---------------- step: final argmax -> next caption ----------------
__global__ void k_argmax()
{
    const int b = blockIdx.x, lane = threadIdx.x;
    float best = -FLT_MAX;
    int   bi   = 0x7FFFFFFF;
    if (lane < 10) { best = g_pmax[b * 10 + lane]; bi = g_pidx[b * 10 + lane]; }
#pragma unroll
    for (int off = 8; off; off >>= 1) {
        const float ov = __shfl_down_sync(0xFFFFFFFF, best, off);
        const int   oi = __shfl_down_sync(0xFFFFFFFF, bi, off);
        if (ov > best || (ov == best && oi < bi)) { best = ov; bi = oi; }
    }
    if (lane == 0) g_cap[b] = bi;
}

// ---------------- launch ----------------
extern "C" void kernel_launch(void* const* d_in, const int* in_sizes, int n_in,
                              void* d_out, int out_size)
{
    (void)in_sizes; (void)n_in; (void)out_size;
    const int*   captions = (const int*)  d_in[0];
    const float* cnn      = (const float*)d_in[1];
    const float* sem      = (const float*)d_in[2];
    const float* Wa       = (const float*)d_in[3];
    const float* Wb       = (const float*)d_in[4];
    const float* Wc       = (const float*)d_in[5];
    const float* Ca       = (const float*)d_in[6];
    const float* Cb       = (const float*)d_in[7];
    const float* Cc       = (const float*)d_in[8];
    const float* Ua       = (const float*)d_in[9];
    const float* Ub       = (const float*)d_in[10];
    const float* Uc       = (const float*)d_in[11];
    const float* bias     = (const float*)d_in[12];
    const float* embed    = (const float*)d_in[13];
    const float* Wl       = (const float*)d_in[14];
    const float* bl       = (const float*)d_in[15];
    float* out = (float*)d_out;

    k_pre1<<<dim3(8, 12),   256>>>(sem, Wb, Ub, Cb);
    k_pre2<<<dim3(8, 4, 4), 256>>>(cnn, Ca);
    k_pre3<<<dim3(8, 4),    256>>>(Cc, bias);
    k_init<<<128, 256>>>(captions);

    for (int t = 0; t < TSTEPS; ++t) {
        k_s1    <<<dim3(8, 8, 2), 256>>>(embed, Wa, Ua);
        k_s2    <<<dim3(8, 4, 4), 256>>>(Wc, Uc);
        k_gates <<<128, 256>>>();
        k_s3    <<<dim3(157, 4),  256>>>(Wl);
        k_logits<<<dim3(10, 64),  256>>>(bl, out, t);
        k_argmax<<<64, 32>>>();
    }
}

// round 9
// speedup vs baseline: 1.0091x; 1.0091x over previous
#include <cuda_runtime.h>
#include <math.h>
#include <float.h>

// SemanticLSTM, GB300 fp32 baseline.
// B=64, T=80 (79 output steps), INPUT=HIDDEN=EMBED=512, SEM=300, CNN=2048, V=10000.
//
// Inputs (metadata order):
//  0 captions(i32 64x80) 1 cnn(64x2048) 2 semantics(64x300)
//  3 Wa(4,512,512) 4 Wb(4,300,512) 5 Wc(4,512,512) 6 Ca(4,2048,512) 7 Cb(4,300,512)
//  8 Cc(4,512,512) 9 Ua(4,512,512) 10 Ub(4,300,512) 11 Uc(4,512,512) 12 bias(4,512)
// 13 embed(10000,512) 14 W_last(512,10000) 15 b_last(10000)
// out: float32 (64, 79, 10000)

#define TSTEPS 79
#define NVOC   10000

// ---------------- scratch (__device__ globals; no allocation) ----------------
__device__ float g_bmul [64*4*1024];   // [b][g][k'] : k'<512 -> bx, k'>=512 -> bh
__device__ float g_bv   [64*4*512];    // bv
__device__ float g_vbias[64*4*512];    // v_feat + bias (time-invariant)
__device__ float g_avp  [4][64*4*512]; // av split-K partials
__device__ float g_s1p  [2][64*4*1024];// raw ax/ah split-K partials (pre bx/bh scale)
__device__ float g_s2p  [4][64*4*512]; // pre split-K partials
__device__ float g_lp   [4][64*NVOC];  // logits split-K partials
__device__ float g_ht   [64*512];
__device__ float g_ct   [64*512];
__device__ float g_pmax [64*10];
__device__ int   g_pidx [64*10];
__device__ int   g_cap  [64];

// ---------------- helpers ----------------
__device__ __forceinline__ float4 f4z() { return make_float4(0.f, 0.f, 0.f, 0.f); }
__device__ __forceinline__ float4 f4add(float4 a, float4 b) {
    return make_float4(a.x+b.x, a.y+b.y, a.z+b.z, a.w+b.w);
}
__device__ __forceinline__ float4 f4mul(float4 a, float4 b) {
    return make_float4(a.x*b.x, a.y*b.y, a.z*b.z, a.w*b.w);
}
__device__ __forceinline__ float4 ld4(const float* p) {
    return *reinterpret_cast<const float4*>(p);
}

// ---------------- shared 64(M) x 64(N) tile GEMM core ----------------
// 256 threads, 4x4 micro-tile per thread. Software prefetch of the next k-tile
// (LDG issued before the FMA loop) hides L2 latency. As is k-major with stride
// 68 (16B-aligned, bank-shifted). loadA4(m,k)/loadB4(k,n) return zero-padded
// float4 fragments; K may be any value (guards in the lambdas).
template<class FA, class FB>
__device__ __forceinline__ void gemm_core(int K, FA loadA4, FB loadB4, float acc[4][4])
{
    __shared__ float As[16][68];
    __shared__ float Bs[16][64];
    const int tid = threadIdx.x;
    const int am  = tid >> 2;          // 0..63  (A row)
    const int ak  = (tid & 3) << 2;    // 0,4,8,12
    const int bk  = tid >> 4;          // 0..15
    const int bn  = (tid & 15) << 2;   // 0..60
    const int tx  = tid & 15;
    const int ty  = tid >> 4;
    const int iters = (K + 15) >> 4;

    float4 a = loadA4(am, ak);
    float4 b = loadB4(bk, bn);
    for (int it = 0; it < iters; ++it) {
        __syncthreads();
        As[ak + 0][am] = a.x;
        As[ak + 1][am] = a.y;
        As[ak + 2][am] = a.z;
        As[ak + 3][am] = a.w;
        *reinterpret_cast<float4*>(&Bs[bk][bn]) = b;
        __syncthreads();
        if (it + 1 < iters) {
            const int k0 = (it + 1) << 4;
            a = loadA4(am, k0 + ak);
            b = loadB4(k0 + bk, bn);
        }
#pragma unroll
        for (int kk = 0; kk < 16; ++kk) {
            float4 av = *reinterpret_cast<const float4*>(&As[kk][ty << 2]);
            float4 bv = *reinterpret_cast<const float4*>(&Bs[kk][tx << 2]);
            float ar[4] = {av.x, av.y, av.z, av.w};
            float br[4] = {bv.x, bv.y, bv.z, bv.w};
#pragma unroll
            for (int r = 0; r < 4; ++r)
#pragma unroll
                for (int c = 0; c < 4; ++c)
                    acc[r][c] = fmaf(ar[r], br[c], acc[r][c]);
        }
    }
}

// ---------------- precompute: bx / bh / bv (semantics @ {Wb,Ub,Cb}[g]) ------
__global__ void k_pre1(const float* __restrict__ sem,
                       const float* __restrict__ Wb,
                       const float* __restrict__ Ub,
                       const float* __restrict__ Cb)
{
    const int nt = blockIdx.x;                 // 0..7  (N tile of 64)
    const int gm = blockIdx.y;                 // 0..11
    const int w  = gm >> 2, g = gm & 3;
    const float* B = (w == 0 ? Wb : (w == 1 ? Ub : Cb)) + g * (300 * 512);
    const int ncol0 = nt << 6;

    float acc[4][4] = {};
    auto la = [&](int m, int k) -> float4 {
        const float* p = sem + m * 300;
        if (k + 4 <= 300) return ld4(p + k);
        float4 r = f4z();
        if (k + 0 < 300) r.x = p[k + 0];
        if (k + 1 < 300) r.y = p[k + 1];
        if (k + 2 < 300) r.z = p[k + 2];
        if (k + 3 < 300) r.w = p[k + 3];
        return r;
    };
    auto lb = [&](int k, int n) -> float4 {
        if (k < 300) return ld4(B + k * 512 + ncol0 + n);
        return f4z();
    };
    gemm_core(300, la, lb, acc);

    const int tx = threadIdx.x & 15, ty = threadIdx.x >> 4;
#pragma unroll
    for (int r = 0; r < 4; ++r) {
        const int b = (ty << 2) + r;
#pragma unroll
        for (int c = 0; c < 4; ++c) {
            const int n = ncol0 + (tx << 2) + c;
            const float v = acc[r][c];
            if (w == 0)      g_bmul[b * 4096 + g * 1024 + n]       = v;
            else if (w == 1) g_bmul[b * 4096 + g * 1024 + 512 + n] = v;
            else             g_bv  [b * 2048 + g * 512 + n]        = v;
        }
    }
}

// ---------------- precompute: av (cnn @ Ca[g]) split-K 4 ----------------
__global__ void k_pre2(const float* __restrict__ cnn, const float* __restrict__ Ca)
{
    const int nt = blockIdx.x, g = blockIdx.y, z = blockIdx.z;
    const int ncol0 = nt << 6;
    const int kc0   = z << 9;                  // *512
    const float* B  = Ca + g * (2048 * 512);

    float acc[4][4] = {};
    auto la = [&](int m, int k) { return ld4(cnn + m * 2048 + kc0 + k); };
    auto lb = [&](int k, int n) { return ld4(B + (kc0 + k) * 512 + ncol0 + n); };
    gemm_core(512, la, lb, acc);

    const int tx = threadIdx.x & 15, ty = threadIdx.x >> 4;
#pragma unroll
    for (int r = 0; r < 4; ++r) {
        const int b = (ty << 2) + r;
#pragma unroll
        for (int c = 0; c < 4; ++c)
            g_avp[z][b * 2048 + g * 512 + ncol0 + (tx << 2) + c] = acc[r][c];
    }
}

// ---------------- precompute: v_feat + bias = ((av)*bv) @ Cc[g] + bias ------
__global__ void k_pre3(const float* __restrict__ Cc, const float* __restrict__ bias)
{
    const int nt = blockIdx.x, g = blockIdx.y;
    const int ncol0 = nt << 6;
    const float* B  = Cc + g * 262144;

    float acc[4][4] = {};
    auto la = [&](int m, int k) -> float4 {
        const int idx = m * 2048 + g * 512 + k;
        float4 s = f4add(f4add(ld4(g_avp[0] + idx), ld4(g_avp[1] + idx)),
                         f4add(ld4(g_avp[2] + idx), ld4(g_avp[3] + idx)));
        return f4mul(s, ld4(g_bv + idx));
    };
    auto lb = [&](int k, int n) { return ld4(B + k * 512 + ncol0 + n); };
    gemm_core(512, la, lb, acc);

    const int tx = threadIdx.x & 15, ty = threadIdx.x >> 4;
#pragma unroll
    for (int r = 0; r < 4; ++r) {
        const int b = (ty << 2) + r;
#pragma unroll
        for (int c = 0; c < 4; ++c) {
            const int n = ncol0 + (tx << 2) + c;
            g_vbias[b * 2048 + g * 512 + n] = acc[r][c] + bias[g * 512 + n];
        }
    }
}

// ---------------- init: h0 = c0 = 0, cap = captions[:,0] ----------------
__global__ void k_init(const int* __restrict__ captions)
{
    const int idx = blockIdx.x * 256 + threadIdx.x;
    if (idx < 64 * 512) { g_ht[idx] = 0.f; g_ct[idx] = 0.f; }
    if (idx < 64) g_cap[idx] = captions[idx * 80];
}

// ---------------- step S1: raw ax / ah partials (split-K 2) ----------------
__global__ void k_s1(const float* __restrict__ embed,
                     const float* __restrict__ Wa,
                     const float* __restrict__ Ua)
{
    const int nt   = blockIdx.x;               // 0..7
    const int gm   = blockIdx.y;               // 0..7
    const int z    = blockIdx.z;               // 0..1
    const int part = gm >> 2, g = gm & 3;      // 0: x path (embed@Wa), 1: h path (ht@Ua)
    const int ncol0 = nt << 6;
    const int kc0   = z << 8;                  // *256
    const float* B  = (part ? Ua : Wa) + g * 262144;

    float acc[4][4] = {};
    auto la = [&](int m, int k) -> float4 {
        const float* p = part ? (g_ht + m * 512) : (embed + g_cap[m] * 512);
        return ld4(p + kc0 + k);
    };
    auto lb = [&](int k, int n) { return ld4(B + (kc0 + k) * 512 + ncol0 + n); };
    gemm_core(256, la, lb, acc);

    const int tx = threadIdx.x & 15, ty = threadIdx.x >> 4;
#pragma unroll
    for (int r = 0; r < 4; ++r) {
        const int b = (ty << 2) + r;
#pragma unroll
        for (int c = 0; c < 4; ++c) {
            const int n = ncol0 + (tx << 2) + c;
            g_s1p[z][b * 4096 + g * 1024 + part * 512 + n] = acc[r][c];
        }
    }
}

// ---------------- step S2: pre partials = (u * bmul) @ [Wc;Uc] (split-K 4) --
__global__ void k_s2(const float* __restrict__ Wc, const float* __restrict__ Uc)
{
    const int nt = blockIdx.x;                 // 0..7
    const int g  = blockIdx.y;                 // 0..3
    const int z  = blockIdx.z;                 // 0..3
    const int ncol0 = nt << 6;
    const int kc0   = z << 8;                  // k' = kc0 + k, k' in [0,1024)
    const float* B  = (z < 2) ? (Wc + g * 262144 + kc0 * 512)
                              : (Uc + g * 262144 + (kc0 - 512) * 512);

    float acc[4][4] = {};
    auto la = [&](int m, int k) -> float4 {
        const int idx = m * 4096 + g * 1024 + kc0 + k;
        float4 s = f4add(ld4(g_s1p[0] + idx), ld4(g_s1p[1] + idx));
        return f4mul(s, ld4(g_bmul + idx));
    };
    auto lb = [&](int k, int n) { return ld4(B + k * 512 + ncol0 + n); };
    gemm_core(256, la, lb, acc);

    const int tx = threadIdx.x & 15, ty = threadIdx.x >> 4;
#pragma unroll
    for (int r = 0; r < 4; ++r) {
        const int b = (ty << 2) + r;
#pragma unroll
        for (int c = 0; c < 4; ++c)
            g_s2p[z][b * 2048 + g * 512 + ncol0 + (tx << 2) + c] = acc[r][c];
    }
}

// ---------------- step gates: pre -> (i,f,o,g) -> ct, ht ----------------
__global__ void k_gates()
{
    const int idx = blockIdx.x * 256 + threadIdx.x; // 0..32767 = b*512 + h
    const int b = idx >> 9, h = idx & 511;
    float pre[4];
#pragma unroll
    for (int g = 0; g < 4; ++g) {
        const int base = b * 2048 + g * 512 + h;
        pre[g] = g_s2p[0][base] + g_s2p[1][base] + g_s2p[2][base] + g_s2p[3][base]
               + g_vbias[base];
    }
    const float ig = 1.f / (1.f + expf(-pre[0]));
    const float fg = 1.f / (1.f + expf(-pre[1]));
    const float og = 1.f / (1.f + expf(-pre[2]));
    const float gg = tanhf(pre[3]);
    const float c  = fg * g_ct[idx] + ig * gg;
    g_ct[idx] = c;
    g_ht[idx] = og * tanhf(c);
}

// ---------------- step S3: logits partials (ht @ W_last, split-K 4) ---------
__global__ void k_s3(const float* __restrict__ Wl)
{
    const int nt = blockIdx.x;                 // 0..156
    const int z  = blockIdx.y;                 // 0..3
    const int ncol0 = nt << 6;
    const int kc0   = z << 7;                  // *128

    float acc[4][4] = {};
    auto la = [&](int m, int k) { return ld4(g_ht + m * 512 + kc0 + k); };
    auto lb = [&](int k, int n) -> float4 {
        const int col = ncol0 + n;
        if (col < NVOC) return ld4(Wl + (kc0 + k) * NVOC + col);  // col mult of 4, NVOC mult of 4
        return f4z();
    };
    gemm_core(128, la, lb, acc);

    const int tx = threadIdx.x & 15, ty = threadIdx.x >> 4;
#pragma unroll
    for (int r = 0; r < 4; ++r) {
        const int b = (ty << 2) + r;
#pragma unroll
        for (int c = 0; c < 4; ++c) {
            const int col = ncol0 + (tx << 2) + c;
            if (col < NVOC) g_lp[z][b * NVOC + col] = acc[r][c];
        }
    }
}

// ---------------- step: combine partials + bias, write out, partial argmax --
__global__ void k_logits(const float* __restrict__ bl, float* __restrict__ out, int t)
{
    const int seg = blockIdx.x;                // 0..9 (1024 cols each)
    const int b   = blockIdx.y;                // 0..63
    const int c0  = seg * 1024 + threadIdx.x * 4;

    float best = -FLT_MAX;
    int   bi   = 0x7FFFFFFF;
    if (c0 < NVOC) {                           // c0 mult of 4 -> full float4 valid
        const int base = b * NVOC + c0;
        float4 v0 = ld4(g_lp[0] + base);
        float4 v1 = ld4(g_lp[1] + base);
        float4 v2 = ld4(g_lp[2] + base);
        float4 v3 = ld4(g_lp[3] + base);
        float4 bb = ld4(bl + c0);
        float v[4] = { v0.x + v1.x + v2.x + v3.x + bb.x,
                       v0.y + v1.y + v2.y + v3.y + bb.y,
                       v0.z + v1.z + v2.z + v3.z + bb.z,
                       v0.w + v1.w + v2.w + v3.w + bb.w };
        *reinterpret_cast<float4*>(out + (b * TSTEPS + t) * NVOC + c0) =
            make_float4(v[0], v[1], v[2], v[3]);
#pragma unroll
        for (int j = 0; j < 4; ++j)
            if (v[j] > best) { best = v[j]; bi = c0 + j; }   // strict > : first index wins
    }

    __shared__ float sv[256];
    __shared__ int   si[256];
    sv[threadIdx.x] = best;
    si[threadIdx.x] = bi;
    __syncthreads();
    for (int s = 128; s; s >>= 1) {
        if (threadIdx.x < s) {
            const float ov = sv[threadIdx.x + s];
            const int   oi = si[threadIdx.x + s];
            if (ov > sv[threadIdx.x] || (ov == sv[threadIdx.x] && oi < si[threadIdx.x])) {
                sv[threadIdx.x] = ov; si[threadIdx.x] = oi;
            }
        }
        __syncthreads();
    }
    if (threadIdx.x == 0) { g_pmax[b * 10 + seg] = sv[0]; g_pidx[b * 10 + seg] = si[0]; }
}

// ---------------- step: final argmax -> next caption ----------------
__global__ void k_argmax()
{
    const int b = blockIdx.x, lane = threadIdx.x;
    float best = -FLT_MAX;
    int   bi   = 0x7FFFFFFF;
    if (lane < 10) { best = g_pmax[b * 10 + lane]; bi = g_pidx[b * 10 + lane]; }
#pragma unroll
    for (int off = 8; off; off >>= 1) {
        const float ov = __shfl_down_sync(0xFFFFFFFF, best, off);
        const int   oi = __shfl_down_sync(0xFFFFFFFF, bi, off);
        if (ov > best || (ov == best && oi < bi)) { best = ov; bi = oi; }
    }
    if (lane == 0) g_cap[b] = bi;
}

// ---------------- launch ----------------
extern "C" void kernel_launch(void* const* d_in, const int* in_sizes, int n_in,
                              void* d_out, int out_size)
{
    (void)in_sizes; (void)n_in; (void)out_size;
    const int*   captions = (const int*)  d_in[0];
    const float* cnn      = (const float*)d_in[1];
    const float* sem      = (const float*)d_in[2];
    const float* Wa       = (const float*)d_in[3];
    const float* Wb       = (const float*)d_in[4];
    const float* Wc       = (const float*)d_in[5];
    const float* Ca       = (const float*)d_in[6];
    const float* Cb       = (const float*)d_in[7];
    const float* Cc       = (const float*)d_in[8];
    const float* Ua       = (const float*)d_in[9];
    const float* Ub       = (const float*)d_in[10];
    const float* Uc       = (const float*)d_in[11];
    const float* bias     = (const float*)d_in[12];
    const float* embed    = (const float*)d_in[13];
    const float* Wl       = (const float*)d_in[14];
    const float* bl       = (const float*)d_in[15];
    float* out = (float*)d_out;

    k_pre1<<<dim3(8, 12),   256>>>(sem, Wb, Ub, Cb);
    k_pre2<<<dim3(8, 4, 4), 256>>>(cnn, Ca);
    k_pre3<<<dim3(8, 4),    256>>>(Cc, bias);
    k_init<<<128, 256>>>(captions);

    for (int t = 0; t < TSTEPS; ++t) {
        k_s1    <<<dim3(8, 8, 2), 256>>>(embed, Wa, Ua);
        k_s2    <<<dim3(8, 4, 4), 256>>>(Wc, Uc);
        k_gates <<<128, 256>>>();
        k_s3    <<<dim3(157, 4),  256>>>(Wl);
        k_logits<<<dim3(10, 64),  256>>>(bl, out, t);
        k_argmax<<<64, 32>>>();
    }
}